// round 3
// baseline (speedup 1.0000x reference)
#include <cuda_runtime.h>

// Problem constants (fixed by metadata): D=64, M=32, output fp32 [n_seg, 2]
#define DIM      64
#define MLEN     32
#define DC       8                     // d-rows per shared tile chunk
#define NCHUNK   (DIM / DC)            // 8
#define TPB      256
#define KPOS     8                     // positions per thread
#define TILE_POS (TPB * KPOS)          // 2048 window starts per block
#define TILE_COLS (TILE_POS + MLEN)    // 2080 columns of X per tile

#define MAX_SEG  8192

__device__ unsigned g_mins[MAX_SEG];

// order-preserving float -> uint mapping (ascending)
__device__ __forceinline__ unsigned enc_f(float f) {
    int b = __float_as_int(f);
    return (unsigned)(b >= 0 ? (b | 0x80000000) : ~b);
}
__device__ __forceinline__ float dec_f(unsigned u) {
    int b = (u & 0x80000000u) ? (int)(u & 0x7FFFFFFFu) : ~(int)u;
    return __int_as_float(b);
}

__global__ void init_mins_kernel(int n) {
    int i = blockIdx.x * blockDim.x + threadIdx.x;
    if (i < n) g_mins[i] = 0xFFFFFFFFu;
}

// Main kernel: per-block tile of 2048 window starts.
// dist[p] = XX[p] - 2*QX[p]   (QQ dropped: constant shift cancels in min-max scale)
__global__ __launch_bounds__(TPB) void shapelet_main_kernel(
    const float* __restrict__ X,      // [DIM, T]
    const float* __restrict__ q,      // [DIM, MLEN]
    const int*   __restrict__ cum,    // [n_seg+1]
    int T, int n_seg, int P)
{
    extern __shared__ float sh[];
    float* tile = sh;                         // [DC][TILE_COLS]
    float* s_sh = sh + DC * TILE_COLS;        // [TILE_COLS]
    float* q_sh = s_sh + TILE_COLS;           // [DC][MLEN]

    const int tid    = threadIdx.x;
    const int pStart = blockIdx.x * TILE_POS;
    const int base   = tid * KPOS;            // local col of this thread's first window

    for (int c = tid; c < TILE_COLS; c += TPB) s_sh[c] = 0.f;

    float acc[KPOS];
#pragma unroll
    for (int k = 0; k < KPOS; ++k) acc[k] = 0.f;

#pragma unroll 1
    for (int dc = 0; dc < NCHUNK; ++dc) {
        __syncthreads();   // prev chunk's readers done before tile overwrite
        // ---- load tile rows (coalesced) ----
#pragma unroll 1
        for (int r = 0; r < DC; ++r) {
            const float* src = X + (size_t)(dc * DC + r) * T;
            for (int c = tid; c < TILE_COLS; c += TPB) {
                int gc = pStart + c;
                tile[r * TILE_COLS + c] = (gc < T) ? src[gc] : 0.f;
            }
        }
        if (tid < DC * MLEN) q_sh[tid] = q[dc * DC * MLEN + tid];
        __syncthreads();

        // ---- accumulate per-column squared sums (each col owned by one thread) ----
        for (int c = tid; c < TILE_COLS; c += TPB) {
            float sum = 0.f;
#pragma unroll
            for (int r = 0; r < DC; ++r) {
                float v = tile[r * TILE_COLS + c];
                sum = fmaf(v, v, sum);
            }
            s_sh[c] += sum;
        }

        // ---- QX accumulation: register-blocked sliding dot products ----
#pragma unroll 1
        for (int r = 0; r < DC; ++r) {
            float xv[KPOS + MLEN];   // 40 floats
            const float4* row = (const float4*)&tile[r * TILE_COLS + base];
#pragma unroll
            for (int i = 0; i < (KPOS + MLEN) / 4; ++i) {
                float4 v = row[i];
                xv[4*i+0] = v.x; xv[4*i+1] = v.y; xv[4*i+2] = v.z; xv[4*i+3] = v.w;
            }
            const float4* qrow = (const float4*)&q_sh[r * MLEN];
#pragma unroll
            for (int j4 = 0; j4 < MLEN / 4; ++j4) {
                float4 qv = qrow[j4];
#pragma unroll
                for (int k = 0; k < KPOS; ++k) {
                    acc[k] = fmaf(xv[4*j4+0+k], qv.x, acc[k]);
                    acc[k] = fmaf(xv[4*j4+1+k], qv.y, acc[k]);
                    acc[k] = fmaf(xv[4*j4+2+k], qv.z, acc[k]);
                    acc[k] = fmaf(xv[4*j4+3+k], qv.w, acc[k]);
                }
            }
        }
    }
    __syncthreads();  // s_sh complete

    // ---- XX via sliding sum over s (vectorized, conflict-free) ----
    float sv[KPOS + MLEN];
    {
        const float4* srow = (const float4*)&s_sh[base];
#pragma unroll
        for (int i = 0; i < (KPOS + MLEN) / 4; ++i) {
            float4 v = srow[i];
            sv[4*i+0] = v.x; sv[4*i+1] = v.y; sv[4*i+2] = v.z; sv[4*i+3] = v.w;
        }
    }
    float dist[KPOS];
    {
        float w = 0.f;
#pragma unroll
        for (int j = 0; j < MLEN; ++j) w += sv[j];
        dist[0] = w - 2.f * acc[0];
#pragma unroll
        for (int k = 1; k < KPOS; ++k) {
            w += sv[k - 1 + MLEN] - sv[k - 1];
            dist[k] = w - 2.f * acc[k];
        }
    }

    // ---- segment assignment + atomic min ----
    int p0 = pStart + base;
    if (p0 < P) {
        // binary search: largest seg with cum[seg] <= p0
        int lo = 0, hi = n_seg - 1;
        while (lo < hi) {
            int mid = (lo + hi + 1) >> 1;
            if (__ldg(&cum[mid]) <= p0) lo = mid; else hi = mid - 1;
        }
        int seg = lo;
        int nxt = __ldg(&cum[seg + 1]);
        unsigned lm = 0xFFFFFFFFu;
#pragma unroll
        for (int k = 0; k < KPOS; ++k) {
            int p = p0 + k;
            if (p >= P) break;
            while (p >= nxt) {
                if (lm != 0xFFFFFFFFu) atomicMin(&g_mins[seg], lm);
                lm = 0xFFFFFFFFu;
                ++seg;
                nxt = __ldg(&cum[seg + 1]);
            }
            if (p + MLEN <= nxt) lm = min(lm, enc_f(dist[k]));
        }
        if (lm != 0xFFFFFFFFu) atomicMin(&g_mins[seg], lm);
    }
}

// Finalize: global min/max over segment mins, scale, linear(1,2)
__global__ void finalize_kernel(const float* __restrict__ lin_w,
                                const float* __restrict__ lin_b,
                                float* __restrict__ out, int n_seg)
{
    __shared__ float sm[4096];
    __shared__ float rlo[32], rhi[32];
    const int tid = threadIdx.x;
    float lo = 3.0e38f, hi = -3.0e38f;
    for (int i = tid; i < n_seg; i += blockDim.x) {
        unsigned u = g_mins[i];
        float v = (u == 0xFFFFFFFFu) ? 1.0e30f : dec_f(u);
        sm[i] = v;
        lo = fminf(lo, v);
        hi = fmaxf(hi, v);
    }
#pragma unroll
    for (int o = 16; o; o >>= 1) {
        lo = fminf(lo, __shfl_xor_sync(0xFFFFFFFFu, lo, o));
        hi = fmaxf(hi, __shfl_xor_sync(0xFFFFFFFFu, hi, o));
    }
    if ((tid & 31) == 0) { rlo[tid >> 5] = lo; rhi[tid >> 5] = hi; }
    __syncthreads();
    const int nw = blockDim.x >> 5;
    if (tid < 32) {
        lo = (tid < nw) ? rlo[tid] : 3.0e38f;
        hi = (tid < nw) ? rhi[tid] : -3.0e38f;
#pragma unroll
        for (int o = 16; o; o >>= 1) {
            lo = fminf(lo, __shfl_xor_sync(0xFFFFFFFFu, lo, o));
            hi = fmaxf(hi, __shfl_xor_sync(0xFFFFFFFFu, hi, o));
        }
        if (tid == 0) { rlo[0] = lo; rhi[0] = hi; }
    }
    __syncthreads();
    lo = rlo[0]; hi = rhi[0];
    const float denom = hi - lo + 1e-16f;
    const float w0 = lin_w[0], w1 = lin_w[1];
    const float b0 = lin_b[0], b1 = lin_b[1];
    for (int i = tid; i < n_seg; i += blockDim.x) {
        float sc = (sm[i] - lo) / denom;
        out[2 * i + 0] = fmaf(sc, w0, b0);
        out[2 * i + 1] = fmaf(sc, w1, b1);
    }
}

extern "C" void kernel_launch(void* const* d_in, const int* in_sizes, int n_in,
                              void* d_out, int out_size)
{
    const float* X     = (const float*)d_in[0];
    const float* query = (const float*)d_in[1];
    const float* lin_w = (const float*)d_in[2];
    const float* lin_b = (const float*)d_in[3];
    const int*   cum   = (const int*)d_in[4];
    float* out = (float*)d_out;

    const int T     = in_sizes[0] / DIM;
    const int n_seg = in_sizes[4] - 1;
    const int P     = T - MLEN + 1;

    const int smem = (DC * TILE_COLS + TILE_COLS + DC * MLEN) * (int)sizeof(float);
    static bool attr_set = false;
    cudaFuncSetAttribute(shapelet_main_kernel,
                         cudaFuncAttributeMaxDynamicSharedMemorySize, smem);
    (void)attr_set;

    init_mins_kernel<<<(n_seg + 255) / 256, 256>>>(n_seg);

    const int nblocks = (P + TILE_POS - 1) / TILE_POS;
    shapelet_main_kernel<<<nblocks, TPB, smem>>>(X, query, cum, T, n_seg, P);

    finalize_kernel<<<1, 1024>>>(lin_w, lin_b, out, n_seg);
}

// round 4
// speedup vs baseline: 1.2531x; 1.2531x over previous
#include <cuda_runtime.h>
#include <stdint.h>

// Problem constants: D=64, M=32, output fp32 [n_seg, 2]
#define DIM      64
#define MLEN     32
#define DC       4                      // d-rows per chunk
#define NCHUNK   (DIM / DC)             // 16
#define TPB      128
#define KPOS     16                     // positions per thread
#define TILE_POS (TPB * KPOS)           // 2048 window starts per block
#define TILE_COLS (TILE_POS + MLEN)     // 2080 columns per tile row
#define NGRAN    (TILE_COLS / 4)        // 520 16B granules per row
// padded row: +4 floats (16B) per 16 floats (64B) -> conflict-free LDS.128
#define RSTRIDE  (TILE_COLS + (TILE_COLS / 16) * 4)   // 2600 floats

#define MAX_SEG  8192

__device__ unsigned g_mins[MAX_SEG];
__device__ int g_done;

// order-preserving float -> uint mapping (ascending)
__device__ __forceinline__ unsigned enc_f(float f) {
    int b = __float_as_int(f);
    return (unsigned)(b >= 0 ? (b | 0x80000000) : ~b);
}
__device__ __forceinline__ float dec_f(unsigned u) {
    int b = (u & 0x80000000u) ? (int)(u & 0x7FFFFFFFu) : ~(int)u;
    return __int_as_float(b);
}

__device__ __forceinline__ unsigned long long ffma2(unsigned long long a,
                                                    unsigned long long b,
                                                    unsigned long long c) {
    unsigned long long d;
    asm("fma.rn.f32x2 %0, %1, %2, %3;" : "=l"(d) : "l"(a), "l"(b), "l"(c));
    return d;
}
__device__ __forceinline__ unsigned long long pk2(float lo, float hi) {
    unsigned long long r;
    asm("mov.b64 %0, {%1, %2};" : "=l"(r) : "f"(lo), "f"(hi));
    return r;
}
__device__ __forceinline__ void up2(unsigned long long v, float& a, float& b) {
    asm("mov.b64 {%0, %1}, %2;" : "=f"(a), "=f"(b) : "l"(v));
}
__device__ __forceinline__ void cpa16(uint32_t dst, const void* src) {
    asm volatile("cp.async.cg.shared.global [%0], [%1], 16;" :: "r"(dst), "l"(src));
}
__device__ __forceinline__ void cpa_commit() {
    asm volatile("cp.async.commit_group;" ::: "memory");
}
__device__ __forceinline__ void cpa_wait1() {
    asm volatile("cp.async.wait_group 1;" ::: "memory");
}

__global__ void init_mins_kernel(int n) {
    int i = blockIdx.x * blockDim.x + threadIdx.x;
    if (i < n) g_mins[i] = 0xFFFFFFFFu;
}

// smem float layout:
//   tile  : [2][DC][RSTRIDE]           floats  0      .. 20800
//   s_sh  : [RSTRIDE]                  floats  20800  .. 23400
//   qd    : [2][DC][3][16] ulonglong   bytes   93600  .. 96672
#define SM_SSH   (2 * DC * RSTRIDE)
#define SM_QD_B  ((SM_SSH + RSTRIDE) * 4)
#define SM_TOTAL (SM_QD_B + 2 * DC * 3 * 16 * 8)

__global__ __launch_bounds__(TPB) void shapelet_main_kernel(
    const float* __restrict__ X,      // [DIM, T]
    const float* __restrict__ q,      // [DIM, MLEN]
    const int*   __restrict__ cum,    // [n_seg+1]
    const float* __restrict__ lin_w,
    const float* __restrict__ lin_b,
    float* __restrict__ out,
    int T, int n_seg, int P)
{
    extern __shared__ float sh[];
    float* s_sh = sh + SM_SSH;
    unsigned long long* qdp = (unsigned long long*)((char*)sh + SM_QD_B);
    const uint32_t sbase = (uint32_t)__cvta_generic_to_shared(sh);

    const int tid    = threadIdx.x;
    const int pStart = blockIdx.x * TILE_POS;

    // zero s_sh (padded slots included; each column owned by one thread)
    for (int c = tid; c < TILE_COLS; c += TPB) {
        int pc = c + ((c >> 4) << 2);
        s_sh[pc] = 0.f;
    }

    unsigned long long accE[8], accO[8], acc15;
    const unsigned long long Z = 0ull;
#pragma unroll
    for (int a = 0; a < 8; ++a) { accE[a] = Z; accO[a] = Z; }
    acc15 = Z;

    // ---- prologue: prefetch chunk 0 ----
    {
#pragma unroll 1
        for (int r = 0; r < DC; ++r) {
            const float* src = X + (size_t)r * T + pStart;
            uint32_t drow = sbase + (uint32_t)(r * RSTRIDE) * 4u;
            float* growp = sh + r * RSTRIDE;
            for (int gi = tid; gi < NGRAN; gi += TPB) {
                int pf = (gi << 2) + ((gi >> 2) << 2);
                int gc = pStart + (gi << 2);
                if (gc + 4 <= T) {
                    cpa16(drow + (uint32_t)pf * 4u, src + (gi << 2));
                } else {
                    float4 z;
                    z.x = (gc + 0 < T) ? src[(gi << 2) + 0] : 0.f;
                    z.y = (gc + 1 < T) ? src[(gi << 2) + 1] : 0.f;
                    z.z = (gc + 2 < T) ? src[(gi << 2) + 2] : 0.f;
                    z.w = (gc + 3 < T) ? src[(gi << 2) + 3] : 0.f;
                    *(float4*)(growp + pf) = z;
                }
            }
        }
        cpa_commit();
    }

#pragma unroll 1
    for (int dc = 0; dc < NCHUNK; ++dc) {
        const int par = dc & 1;
        // prefetch next chunk into other buffer
        if (dc + 1 < NCHUNK) {
            const int par2 = (dc + 1) & 1;
#pragma unroll 1
            for (int r = 0; r < DC; ++r) {
                const float* src = X + (size_t)((dc + 1) * DC + r) * T + pStart;
                uint32_t drow = sbase + (uint32_t)((par2 * DC + r) * RSTRIDE) * 4u;
                float* growp = sh + (par2 * DC + r) * RSTRIDE;
                for (int gi = tid; gi < NGRAN; gi += TPB) {
                    int pf = (gi << 2) + ((gi >> 2) << 2);
                    int gc = pStart + (gi << 2);
                    if (gc + 4 <= T) {
                        cpa16(drow + (uint32_t)pf * 4u, src + (gi << 2));
                    } else {
                        float4 z;
                        z.x = (gc + 0 < T) ? src[(gi << 2) + 0] : 0.f;
                        z.y = (gc + 1 < T) ? src[(gi << 2) + 1] : 0.f;
                        z.z = (gc + 2 < T) ? src[(gi << 2) + 2] : 0.f;
                        z.w = (gc + 3 < T) ? src[(gi << 2) + 3] : 0.f;
                        *(float4*)(growp + pf) = z;
                    }
                }
            }
        }
        // write duplicated query pairs for this chunk
        for (int e = tid; e < DC * 48; e += TPB) {
            int r = e / 48;
            int rem = e - r * 48;
            int kind = rem >> 4;
            int t = rem & 15;
            const float* qr = q + (dc * DC + r) * MLEN;
            float a = qr[2 * t], b = qr[2 * t + 1];
            unsigned long long v = (kind == 0) ? pk2(a, a)
                                 : (kind == 1) ? pk2(b, b)
                                               : pk2(b, 0.f);
            qdp[par * (DC * 48) + e] = v;
        }
        cpa_commit();
        cpa_wait1();          // current chunk's data landed
        __syncthreads();

        // ---- compute on buffer par ----
        const float* tb = sh + par * DC * RSTRIDE;
        const unsigned long long* qdR = qdp + par * (DC * 48);
#pragma unroll 1
        for (int r = 0; r < DC; ++r) {
            unsigned long long xq[24];
            const float* rowp = tb + r * RSTRIDE;
#pragma unroll
            for (int i = 0; i < 12; ++i) {
                int g = (tid << 2) + i;
                int pf = (g << 2) + ((g >> 2) << 2);
                ulonglong2 vv = *(const ulonglong2*)(rowp + pf);
                xq[2 * i] = vv.x; xq[2 * i + 1] = vv.y;
            }
            const unsigned long long* qr = qdR + r * 48;
#pragma unroll
            for (int t = 0; t < 16; ++t) {
                unsigned long long qe = qr[t];
                unsigned long long qo = qr[16 + t];
                unsigned long long q5 = qr[32 + t];
#pragma unroll
                for (int a = 0; a < 8; ++a) {
                    accE[a] = ffma2(xq[t + a], qe, accE[a]);
                    accO[a] = ffma2(xq[t + a], qo, accO[a]);
                }
                acc15 = ffma2(xq[t + 8], q5, acc15);
            }
        }
        // per-column squared sums (column owned by one thread; no extra sync)
        for (int c = tid; c < TILE_COLS; c += TPB) {
            int pc = c + ((c >> 4) << 2);
            float s = 0.f;
#pragma unroll
            for (int r = 0; r < DC; ++r) {
                float v = tb[r * RSTRIDE + pc];
                s = fmaf(v, v, s);
            }
            s_sh[pc] += s;
        }
        __syncthreads();
    }

    // ---- assemble distances ----
    float sv[48];
#pragma unroll
    for (int i = 0; i < 12; ++i) {
        int g = (tid << 2) + i;
        int pf = (g << 2) + ((g >> 2) << 2);
        float4 f = *(const float4*)(s_sh + pf);
        sv[4 * i + 0] = f.x; sv[4 * i + 1] = f.y;
        sv[4 * i + 2] = f.z; sv[4 * i + 3] = f.w;
    }
    float qx[16];
    {
        float el[8], eh[8], ol[8], oh[8], l15, h15;
#pragma unroll
        for (int a = 0; a < 8; ++a) {
            up2(accE[a], el[a], eh[a]);
            up2(accO[a], ol[a], oh[a]);
        }
        up2(acc15, l15, h15);
#pragma unroll
        for (int a = 0; a < 8; ++a) {
            qx[2 * a]     = el[a] + oh[a];
            qx[2 * a + 1] = eh[a] + ((a < 7) ? ol[a + 1] : l15);
        }
    }
    float dist[KPOS];
    {
        float w = 0.f;
#pragma unroll
        for (int j = 0; j < MLEN; ++j) w += sv[j];
        dist[0] = w - 2.f * qx[0];
#pragma unroll
        for (int k = 1; k < KPOS; ++k) {
            w += sv[k - 1 + MLEN] - sv[k - 1];
            dist[k] = w - 2.f * qx[k];
        }
    }

    // ---- segment assignment + atomic min ----
    int p0 = pStart + (tid << 4);
    if (p0 < P) {
        int lo = 0, hi = n_seg - 1;
        while (lo < hi) {
            int mid = (lo + hi + 1) >> 1;
            if (__ldg(&cum[mid]) <= p0) lo = mid; else hi = mid - 1;
        }
        int seg = lo;
        int nxt = __ldg(&cum[seg + 1]);
        unsigned lm = 0xFFFFFFFFu;
#pragma unroll
        for (int k = 0; k < KPOS; ++k) {
            int p = p0 + k;
            if (p >= P) break;
            while (p >= nxt) {
                if (lm != 0xFFFFFFFFu) atomicMin(&g_mins[seg], lm);
                lm = 0xFFFFFFFFu;
                ++seg;
                nxt = __ldg(&cum[seg + 1]);
            }
            if (p + MLEN <= nxt) lm = min(lm, enc_f(dist[k]));
        }
        if (lm != 0xFFFFFFFFu) atomicMin(&g_mins[seg], lm);
    }

    // ---- fused finalize: last block does min/max + scale + linear ----
    __threadfence();
    __syncthreads();
    __shared__ int s_last;
    __shared__ float rlo[4], rhi[4];
    if (tid == 0) s_last = (atomicAdd(&g_done, 1) == (int)gridDim.x - 1);
    __syncthreads();
    if (s_last) {
        __threadfence();
        float flo = 3.0e38f, fhi = -3.0e38f;
        for (int i = tid; i < n_seg; i += TPB) {
            unsigned u = g_mins[i];
            float v = (u == 0xFFFFFFFFu) ? 1.0e30f : dec_f(u);
            flo = fminf(flo, v);
            fhi = fmaxf(fhi, v);
        }
#pragma unroll
        for (int o = 16; o; o >>= 1) {
            flo = fminf(flo, __shfl_xor_sync(0xFFFFFFFFu, flo, o));
            fhi = fmaxf(fhi, __shfl_xor_sync(0xFFFFFFFFu, fhi, o));
        }
        if ((tid & 31) == 0) { rlo[tid >> 5] = flo; rhi[tid >> 5] = fhi; }
        __syncthreads();
        flo = fminf(fminf(rlo[0], rlo[1]), fminf(rlo[2], rlo[3]));
        fhi = fmaxf(fmaxf(rhi[0], rhi[1]), fmaxf(rhi[2], rhi[3]));
        const float denom = fhi - flo + 1e-16f;
        const float w0 = lin_w[0], w1 = lin_w[1];
        const float b0 = lin_b[0], b1 = lin_b[1];
        for (int i = tid; i < n_seg; i += TPB) {
            unsigned u = g_mins[i];
            float v = (u == 0xFFFFFFFFu) ? 1.0e30f : dec_f(u);
            float sc = (v - flo) / denom;
            out[2 * i + 0] = fmaf(sc, w0, b0);
            out[2 * i + 1] = fmaf(sc, w1, b1);
        }
        if (tid == 0) g_done = 0;
    }
}

extern "C" void kernel_launch(void* const* d_in, const int* in_sizes, int n_in,
                              void* d_out, int out_size)
{
    const float* X     = (const float*)d_in[0];
    const float* query = (const float*)d_in[1];
    const float* lin_w = (const float*)d_in[2];
    const float* lin_b = (const float*)d_in[3];
    const int*   cum   = (const int*)d_in[4];
    float* out = (float*)d_out;

    const int T     = in_sizes[0] / DIM;
    const int n_seg = in_sizes[4] - 1;
    const int P     = T - MLEN + 1;

    cudaFuncSetAttribute(shapelet_main_kernel,
                         cudaFuncAttributeMaxDynamicSharedMemorySize, SM_TOTAL);

    init_mins_kernel<<<(n_seg + 255) / 256, 256>>>(n_seg);

    const int nblocks = (P + TILE_POS - 1) / TILE_POS;
    shapelet_main_kernel<<<nblocks, TPB, SM_TOTAL>>>(
        X, query, cum, lin_w, lin_b, out, T, n_seg, P);
}

// round 5
// speedup vs baseline: 1.4615x; 1.1662x over previous
#include <cuda_runtime.h>
#include <stdint.h>

// Problem constants: D=64, M=32, output fp32 [n_seg, 2]
#define DIM      64
#define MLEN     32
#define DC       2                      // d-rows per chunk
#define NCHUNK   (DIM / DC)             // 32
#define TPB      256
#define KPOS     8                      // positions per thread
#define TILE_POS (TPB * KPOS)           // 2048 window starts per block
#define TILE_COLS (TILE_POS + MLEN)     // 2080 columns per tile row
#define NGRAN    (TILE_COLS / 4)        // 520 16B granules per row
// pad 1 granule (16B) per 8 granules (128B): conflict-free for stride-2-granule lanes
#define RSTRIDE  (TILE_COLS + (TILE_COLS / 32) * 4)   // 2340 floats

#define MAX_SEG  8192

__device__ unsigned g_mins[MAX_SEG];
__device__ int g_done;

// order-preserving float -> uint mapping (ascending)
__device__ __forceinline__ unsigned enc_f(float f) {
    int b = __float_as_int(f);
    return (unsigned)(b >= 0 ? (b | 0x80000000) : ~b);
}
__device__ __forceinline__ float dec_f(unsigned u) {
    int b = (u & 0x80000000u) ? (int)(u & 0x7FFFFFFFu) : ~(int)u;
    return __int_as_float(b);
}

__device__ __forceinline__ unsigned long long ffma2(unsigned long long a,
                                                    unsigned long long b,
                                                    unsigned long long c) {
    unsigned long long d;
    asm("fma.rn.f32x2 %0, %1, %2, %3;" : "=l"(d) : "l"(a), "l"(b), "l"(c));
    return d;
}
__device__ __forceinline__ unsigned long long pk2(float lo, float hi) {
    unsigned long long r;
    asm("mov.b64 %0, {%1, %2};" : "=l"(r) : "f"(lo), "f"(hi));
    return r;
}
__device__ __forceinline__ void up2(unsigned long long v, float& a, float& b) {
    asm("mov.b64 {%0, %1}, %2;" : "=f"(a), "=f"(b) : "l"(v));
}
__device__ __forceinline__ void cpa16(uint32_t dst, const void* src) {
    asm volatile("cp.async.cg.shared.global [%0], [%1], 16;" :: "r"(dst), "l"(src));
}
__device__ __forceinline__ void cpa_commit() {
    asm volatile("cp.async.commit_group;" ::: "memory");
}
__device__ __forceinline__ void cpa_wait1() {
    asm volatile("cp.async.wait_group 1;" ::: "memory");
}

__global__ void init_mins_kernel(int n) {
    int i = blockIdx.x * blockDim.x + threadIdx.x;
    if (i < n) g_mins[i] = 0xFFFFFFFFu;
}

// smem float layout:
//   tile : [2][DC][RSTRIDE]   floats 0 .. 9360
//   s_sh : [RSTRIDE]          floats 9360 .. 11700
//   qd   : [2][DC][2][16] ull bytes 46800 .. 47824
#define SM_SSH   (2 * DC * RSTRIDE)
#define SM_QD_B  ((SM_SSH + RSTRIDE) * 4)
#define SM_TOTAL (SM_QD_B + 2 * DC * 2 * 16 * 8)

__global__ __launch_bounds__(TPB, 3) void shapelet_main_kernel(
    const float* __restrict__ X,      // [DIM, T]
    const float* __restrict__ q,      // [DIM, MLEN]
    const int*   __restrict__ cum,    // [n_seg+1]
    const float* __restrict__ lin_w,
    const float* __restrict__ lin_b,
    float* __restrict__ out,
    int T, int n_seg, int P)
{
    extern __shared__ float sh[];
    float* s_sh = sh + SM_SSH;
    unsigned long long* qdp = (unsigned long long*)((char*)sh + SM_QD_B);
    const uint32_t sbase = (uint32_t)__cvta_generic_to_shared(sh);

    const int tid    = threadIdx.x;
    const int pStart = blockIdx.x * TILE_POS;
    const bool inb   = (pStart + TILE_COLS <= T);

    for (int c = tid; c < TILE_COLS; c += TPB) {
        int pc = c + ((c >> 5) << 2);
        s_sh[pc] = 0.f;
    }

    unsigned long long accE[4], accO[5];
#pragma unroll
    for (int a = 0; a < 4; ++a) accE[a] = 0ull;
#pragma unroll
    for (int a = 0; a < 5; ++a) accO[a] = 0ull;

    // ---- prefetch one chunk into buffer b ----
    auto prefetch = [&](int dc, int b) {
#pragma unroll
        for (int r = 0; r < DC; ++r) {
            const float* src = X + (size_t)(dc * DC + r) * T + pStart;
            uint32_t drow = sbase + (uint32_t)((b * DC + r) * RSTRIDE) * 4u;
            float* growp = sh + (b * DC + r) * RSTRIDE;
            if (inb) {
                for (int gi = tid; gi < NGRAN; gi += TPB) {
                    int pf = (gi + (gi >> 3)) << 2;
                    cpa16(drow + (uint32_t)pf * 4u, src + (gi << 2));
                }
            } else {
                for (int gi = tid; gi < NGRAN; gi += TPB) {
                    int pf = (gi + (gi >> 3)) << 2;
                    int gc = pStart + (gi << 2);
                    if (gc + 4 <= T) {
                        cpa16(drow + (uint32_t)pf * 4u, src + (gi << 2));
                    } else {
                        float4 z;
                        z.x = (gc + 0 < T) ? src[(gi << 2) + 0] : 0.f;
                        z.y = (gc + 1 < T) ? src[(gi << 2) + 1] : 0.f;
                        z.z = (gc + 2 < T) ? src[(gi << 2) + 2] : 0.f;
                        z.w = (gc + 3 < T) ? src[(gi << 2) + 3] : 0.f;
                        *(float4*)(growp + pf) = z;
                    }
                }
            }
        }
    };

    prefetch(0, 0);
    cpa_commit();

#pragma unroll 1
    for (int dc = 0; dc < NCHUNK; ++dc) {
        const int par = dc & 1;
        if (dc + 1 < NCHUNK) prefetch(dc + 1, (dc + 1) & 1);
        // duplicated query pairs for this chunk: [r][kind][t], t contiguous
        if (tid < DC * 2 * 16) {
            int r    = tid >> 5;
            int kind = (tid >> 4) & 1;
            int t    = tid & 15;
            float v = q[(dc * DC + r) * MLEN + 2 * t + kind];
            qdp[((par * DC + r) * 2 + kind) * 16 + t] = pk2(v, v);
        }
        cpa_commit();
        cpa_wait1();
        __syncthreads();

        const float* tb = sh + par * DC * RSTRIDE;
        const unsigned long long* qdR = qdp + par * DC * 32;
#pragma unroll
        for (int r = 0; r < DC; ++r) {
            unsigned long long xq[20];
            const float* rowp = tb + r * RSTRIDE;
#pragma unroll
            for (int i = 0; i < 10; ++i) {
                int g = 2 * tid + i;
                int pf = (g + (g >> 3)) << 2;
                ulonglong2 vv = *(const ulonglong2*)(rowp + pf);
                xq[2 * i] = vv.x; xq[2 * i + 1] = vv.y;
            }
            const unsigned long long* qr = qdR + r * 32;
#pragma unroll
            for (int t2 = 0; t2 < 8; ++t2) {
                ulonglong2 qe2 = *(const ulonglong2*)(qr + 2 * t2);
                ulonglong2 qo2 = *(const ulonglong2*)(qr + 16 + 2 * t2);
                const int t = 2 * t2;
#pragma unroll
                for (int a = 0; a < 4; ++a)
                    accE[a] = ffma2(xq[t + a], qe2.x, accE[a]);
#pragma unroll
                for (int a = 0; a < 5; ++a)
                    accO[a] = ffma2(xq[t + a], qo2.x, accO[a]);
#pragma unroll
                for (int a = 0; a < 4; ++a)
                    accE[a] = ffma2(xq[t + 1 + a], qe2.y, accE[a]);
#pragma unroll
                for (int a = 0; a < 5; ++a)
                    accO[a] = ffma2(xq[t + 1 + a], qo2.y, accO[a]);
            }
        }
        // per-column squared sums (owner-computes)
        for (int c = tid; c < TILE_COLS; c += TPB) {
            int pc = c + ((c >> 5) << 2);
            float s = 0.f;
#pragma unroll
            for (int r = 0; r < DC; ++r) {
                float v = tb[r * RSTRIDE + pc];
                s = fmaf(v, v, s);
            }
            s_sh[pc] += s;
        }
        __syncthreads();
    }

    // ---- assemble distances ----
    float sv[KPOS + MLEN];
#pragma unroll
    for (int i = 0; i < 10; ++i) {
        int g = 2 * tid + i;
        int pf = (g + (g >> 3)) << 2;
        float4 f = *(const float4*)(s_sh + pf);
        sv[4 * i + 0] = f.x; sv[4 * i + 1] = f.y;
        sv[4 * i + 2] = f.z; sv[4 * i + 3] = f.w;
    }
    float qx[KPOS];
    {
        float el[4], eh[4], ol[5], oh[5];
#pragma unroll
        for (int a = 0; a < 4; ++a) up2(accE[a], el[a], eh[a]);
#pragma unroll
        for (int a = 0; a < 5; ++a) up2(accO[a], ol[a], oh[a]);
#pragma unroll
        for (int a = 0; a < 4; ++a) {
            qx[2 * a]     = el[a] + oh[a];
            qx[2 * a + 1] = eh[a] + ol[a + 1];
        }
    }
    float dist[KPOS];
    {
        float w = 0.f;
#pragma unroll
        for (int j = 0; j < MLEN; ++j) w += sv[j];
        dist[0] = w - 2.f * qx[0];
#pragma unroll
        for (int k = 1; k < KPOS; ++k) {
            w += sv[k - 1 + MLEN] - sv[k - 1];
            dist[k] = w - 2.f * qx[k];
        }
    }

    // ---- segment assignment + atomic min ----
    int p0 = pStart + tid * KPOS;
    if (p0 < P) {
        int lo = 0, hi = n_seg - 1;
        while (lo < hi) {
            int mid = (lo + hi + 1) >> 1;
            if (__ldg(&cum[mid]) <= p0) lo = mid; else hi = mid - 1;
        }
        int seg = lo;
        int nxt = __ldg(&cum[seg + 1]);
        unsigned lm = 0xFFFFFFFFu;
#pragma unroll
        for (int k = 0; k < KPOS; ++k) {
            int p = p0 + k;
            if (p >= P) break;
            while (p >= nxt) {
                if (lm != 0xFFFFFFFFu) atomicMin(&g_mins[seg], lm);
                lm = 0xFFFFFFFFu;
                ++seg;
                nxt = __ldg(&cum[seg + 1]);
            }
            if (p + MLEN <= nxt) lm = min(lm, enc_f(dist[k]));
        }
        if (lm != 0xFFFFFFFFu) atomicMin(&g_mins[seg], lm);
    }

    // ---- fused finalize: last block does min/max + scale + linear ----
    __threadfence();
    __syncthreads();
    __shared__ int s_last;
    __shared__ float rlo[8], rhi[8];
    if (tid == 0) s_last = (atomicAdd(&g_done, 1) == (int)gridDim.x - 1);
    __syncthreads();
    if (s_last) {
        __threadfence();
        float flo = 3.0e38f, fhi = -3.0e38f;
        for (int i = tid; i < n_seg; i += TPB) {
            unsigned u = g_mins[i];
            float v = (u == 0xFFFFFFFFu) ? 1.0e30f : dec_f(u);
            flo = fminf(flo, v);
            fhi = fmaxf(fhi, v);
        }
#pragma unroll
        for (int o = 16; o; o >>= 1) {
            flo = fminf(flo, __shfl_xor_sync(0xFFFFFFFFu, flo, o));
            fhi = fmaxf(fhi, __shfl_xor_sync(0xFFFFFFFFu, fhi, o));
        }
        if ((tid & 31) == 0) { rlo[tid >> 5] = flo; rhi[tid >> 5] = fhi; }
        __syncthreads();
        if (tid < 32) {
            flo = (tid < 8) ? rlo[tid] : 3.0e38f;
            fhi = (tid < 8) ? rhi[tid] : -3.0e38f;
#pragma unroll
            for (int o = 4; o; o >>= 1) {
                flo = fminf(flo, __shfl_xor_sync(0xFFFFFFFFu, flo, o));
                fhi = fmaxf(fhi, __shfl_xor_sync(0xFFFFFFFFu, fhi, o));
            }
            if (tid == 0) { rlo[0] = flo; rhi[0] = fhi; }
        }
        __syncthreads();
        flo = rlo[0]; fhi = rhi[0];
        const float denom = fhi - flo + 1e-16f;
        const float w0 = lin_w[0], w1 = lin_w[1];
        const float b0 = lin_b[0], b1 = lin_b[1];
        for (int i = tid; i < n_seg; i += TPB) {
            unsigned u = g_mins[i];
            float v = (u == 0xFFFFFFFFu) ? 1.0e30f : dec_f(u);
            float sc = (v - flo) / denom;
            out[2 * i + 0] = fmaf(sc, w0, b0);
            out[2 * i + 1] = fmaf(sc, w1, b1);
        }
        if (tid == 0) g_done = 0;
    }
}

extern "C" void kernel_launch(void* const* d_in, const int* in_sizes, int n_in,
                              void* d_out, int out_size)
{
    const float* X     = (const float*)d_in[0];
    const float* query = (const float*)d_in[1];
    const float* lin_w = (const float*)d_in[2];
    const float* lin_b = (const float*)d_in[3];
    const int*   cum   = (const int*)d_in[4];
    float* out = (float*)d_out;

    const int T     = in_sizes[0] / DIM;
    const int n_seg = in_sizes[4] - 1;
    const int P     = T - MLEN + 1;

    cudaFuncSetAttribute(shapelet_main_kernel,
                         cudaFuncAttributeMaxDynamicSharedMemorySize, SM_TOTAL);

    init_mins_kernel<<<(n_seg + 255) / 256, 256>>>(n_seg);

    const int nblocks = (P + TILE_POS - 1) / TILE_POS;
    shapelet_main_kernel<<<nblocks, TPB, SM_TOTAL>>>(
        X, query, cum, lin_w, lin_b, out, T, n_seg, P);
}

// round 7
// speedup vs baseline: 1.5700x; 1.0742x over previous
#include <cuda_runtime.h>
#include <stdint.h>

// Problem constants: D=64, M=32, output fp32 [n_seg, 2]
#define DIM      64
#define MLEN     32
#define DC       2                      // d-rows per chunk
#define NCHUNK   (DIM / DC)             // 32
#define TPB      256
#define KPOS     8                      // positions per thread
#define TILE_POS (TPB * KPOS)           // 2048 window starts per block
#define TILE_COLS (TILE_POS + MLEN)     // 2080 columns per tile row
#define NGRAN    (TILE_COLS / 4)        // 520 16B granules per row
// pad 1 granule (16B) per 8 granules (128B): conflict-free for stride-2-granule lanes
#define RSTRIDE  (TILE_COLS + (TILE_COLS / 32) * 4)   // 2340 floats

#define MAX_SEG  8192

__device__ unsigned g_mins[MAX_SEG];
__device__ int g_done;

// order-preserving float -> uint mapping (ascending)
__device__ __forceinline__ unsigned enc_f(float f) {
    int b = __float_as_int(f);
    return (unsigned)(b >= 0 ? (b | 0x80000000) : ~b);
}
__device__ __forceinline__ float dec_f(unsigned u) {
    int b = (u & 0x80000000u) ? (int)(u & 0x7FFFFFFFu) : ~(int)u;
    return __int_as_float(b);
}

__device__ __forceinline__ unsigned long long ffma2(unsigned long long a,
                                                    unsigned long long b,
                                                    unsigned long long c) {
    unsigned long long d;
    asm("fma.rn.f32x2 %0, %1, %2, %3;" : "=l"(d) : "l"(a), "l"(b), "l"(c));
    return d;
}
__device__ __forceinline__ unsigned long long pk2(float lo, float hi) {
    unsigned long long r;
    asm("mov.b64 %0, {%1, %2};" : "=l"(r) : "f"(lo), "f"(hi));
    return r;
}
__device__ __forceinline__ void up2(unsigned long long v, float& a, float& b) {
    asm("mov.b64 {%0, %1}, %2;" : "=f"(a), "=f"(b) : "l"(v));
}
__device__ __forceinline__ void cpa16(uint32_t dst, const void* src) {
    asm volatile("cp.async.cg.shared.global [%0], [%1], 16;" :: "r"(dst), "l"(src));
}
__device__ __forceinline__ void cpa_commit() {
    asm volatile("cp.async.commit_group;" ::: "memory");
}
__device__ __forceinline__ void cpa_wait1() {
    asm volatile("cp.async.wait_group 1;" ::: "memory");
}

__global__ void init_mins_kernel(int n) {
    int i = blockIdx.x * blockDim.x + threadIdx.x;
    if (i < n) g_mins[i] = 0xFFFFFFFFu;
}

// smem float layout:
//   tile : [2][DC][RSTRIDE]          floats 0 .. 9360
//   s_sh : [RSTRIDE]                 floats 9360 .. 11700
//   qd   : [2][DC][2][2][8] ull      bytes 46800 .. 47824
#define SM_SSH   (2 * DC * RSTRIDE)
#define SM_QD_B  ((SM_SSH + RSTRIDE) * 4)
#define SM_TOTAL (SM_QD_B + 2 * DC * 2 * 2 * 8 * 8)

__global__ __launch_bounds__(TPB, 4) void shapelet_main_kernel(
    const float* __restrict__ X,      // [DIM, T]
    const float* __restrict__ q,      // [DIM, MLEN]
    const int*   __restrict__ cum,    // [n_seg+1]
    const float* __restrict__ lin_w,
    const float* __restrict__ lin_b,
    float* __restrict__ out,
    int T, int n_seg, int P)
{
    extern __shared__ float sh[];
    float* s_sh = sh + SM_SSH;
    unsigned long long* qdp = (unsigned long long*)((char*)sh + SM_QD_B);
    const uint32_t sbase = (uint32_t)__cvta_generic_to_shared(sh);

    const int tid    = threadIdx.x;
    const int pStart = blockIdx.x * TILE_POS;
    const bool inb   = (pStart + TILE_COLS <= T);

    unsigned long long accE[4], accO[5], sq[4];
#pragma unroll
    for (int a = 0; a < 4; ++a) { accE[a] = 0ull; sq[a] = 0ull; }
#pragma unroll
    for (int a = 0; a < 5; ++a) accO[a] = 0ull;
    float tacc = 0.f;                       // tail col (warp 0 only)
    const int tailpc = (2048 + tid) + (((2048 + tid) >> 5) << 2);

    // ---- prefetch one chunk into buffer b ----
    auto prefetch = [&](int dc, int b) {
#pragma unroll
        for (int r = 0; r < DC; ++r) {
            const float* src = X + (size_t)(dc * DC + r) * T + pStart;
            uint32_t drow = sbase + (uint32_t)((b * DC + r) * RSTRIDE) * 4u;
            float* growp = sh + (b * DC + r) * RSTRIDE;
            if (inb) {
                for (int gi = tid; gi < NGRAN; gi += TPB) {
                    int pf = (gi + (gi >> 3)) << 2;
                    cpa16(drow + (uint32_t)pf * 4u, src + (gi << 2));
                }
            } else {
                for (int gi = tid; gi < NGRAN; gi += TPB) {
                    int pf = (gi + (gi >> 3)) << 2;
                    int gc = pStart + (gi << 2);
                    if (gc + 4 <= T) {
                        cpa16(drow + (uint32_t)pf * 4u, src + (gi << 2));
                    } else {
                        float4 z;
                        z.x = (gc + 0 < T) ? src[(gi << 2) + 0] : 0.f;
                        z.y = (gc + 1 < T) ? src[(gi << 2) + 1] : 0.f;
                        z.z = (gc + 2 < T) ? src[(gi << 2) + 2] : 0.f;
                        z.w = (gc + 3 < T) ? src[(gi << 2) + 3] : 0.f;
                        *(float4*)(growp + pf) = z;
                    }
                }
            }
        }
    };

    prefetch(0, 0);
    cpa_commit();

#pragma unroll 1
    for (int dc = 0; dc < NCHUNK; ++dc) {
        const int par = dc & 1;
        if (dc + 1 < NCHUNK) prefetch(dc + 1, (dc + 1) & 1);
        // duplicated query pairs: [r][half][kind][t], tap j = 16*half + 2*t + kind
        if (tid < DC * 2 * 2 * 8) {
            int r    = tid >> 5;
            int half = (tid >> 4) & 1;
            int kind = (tid >> 3) & 1;
            int t    = tid & 7;
            float v = q[(dc * DC + r) * MLEN + 16 * half + 2 * t + kind];
            qdp[(((par * DC + r) * 2 + half) * 2 + kind) * 8 + t] = pk2(v, v);
        }
        cpa_commit();
        cpa_wait1();
        __syncthreads();

        const float* tb = sh + par * DC * RSTRIDE;
        const unsigned long long* qdR = qdp + par * (DC * 32);
#pragma unroll
        for (int r = 0; r < DC; ++r) {
            const float* rowp = tb + r * RSTRIDE;
#pragma unroll
            for (int h = 0; h < 2; ++h) {
                unsigned long long xq[12];
#pragma unroll
                for (int i = 0; i < 6; ++i) {
                    int g = 2 * tid + 4 * h + i;
                    int pf = (g + (g >> 3)) << 2;
                    ulonglong2 vv = *(const ulonglong2*)(rowp + pf);
                    xq[2 * i] = vv.x; xq[2 * i + 1] = vv.y;
                }
                if (h == 0) {
#pragma unroll
                    for (int j = 0; j < 4; ++j)
                        sq[j] = ffma2(xq[j], xq[j], sq[j]);
                }
                const unsigned long long* qr = qdR + (r * 2 + h) * 16;
#pragma unroll
                for (int t2 = 0; t2 < 8; ++t2) {
                    unsigned long long qe = qr[t2];
                    unsigned long long qo = qr[8 + t2];
#pragma unroll
                    for (int a = 0; a < 4; ++a)
                        accE[a] = ffma2(xq[t2 + a], qe, accE[a]);
#pragma unroll
                    for (int a = 0; a < 5; ++a)
                        accO[a] = ffma2(xq[t2 + a], qo, accO[a]);
                }
            }
        }
        // tail columns 2048..2079: squared sums by warp 0 (register-resident)
        if (tid < 32) {
#pragma unroll
            for (int r = 0; r < DC; ++r) {
                float v = tb[r * RSTRIDE + tailpc];
                tacc = fmaf(v, v, tacc);
            }
        }
        __syncthreads();
    }

    // ---- write per-column squared sums once ----
    {
        int c0 = 8 * tid;
        int pc = c0 + ((c0 >> 5) << 2);
        ulonglong2 a; a.x = sq[0]; a.y = sq[1];
        ulonglong2 b; b.x = sq[2]; b.y = sq[3];
        *(ulonglong2*)(s_sh + pc) = a;
        *(ulonglong2*)(s_sh + pc + 4) = b;
    }
    if (tid < 32) s_sh[tailpc] = tacc;
    __syncthreads();

    // ---- assemble distances ----
    float sv[KPOS + MLEN];
#pragma unroll
    for (int i = 0; i < 10; ++i) {
        int g = 2 * tid + i;
        int pf = (g + (g >> 3)) << 2;
        float4 f = *(const float4*)(s_sh + pf);
        sv[4 * i + 0] = f.x; sv[4 * i + 1] = f.y;
        sv[4 * i + 2] = f.z; sv[4 * i + 3] = f.w;
    }
    float qx[KPOS];
    {
        float el[4], eh[4], ol[5], oh[5];
#pragma unroll
        for (int a = 0; a < 4; ++a) up2(accE[a], el[a], eh[a]);
#pragma unroll
        for (int a = 0; a < 5; ++a) up2(accO[a], ol[a], oh[a]);
#pragma unroll
        for (int a = 0; a < 4; ++a) {
            qx[2 * a]     = el[a] + oh[a];
            qx[2 * a + 1] = eh[a] + ol[a + 1];
        }
    }
    float dist[KPOS];
    {
        float w = 0.f;
#pragma unroll
        for (int j = 0; j < MLEN; ++j) w += sv[j];
        dist[0] = w - 2.f * qx[0];
#pragma unroll
        for (int k = 1; k < KPOS; ++k) {
            w += sv[k - 1 + MLEN] - sv[k - 1];
            dist[k] = w - 2.f * qx[k];
        }
    }

    // ---- segment assignment + atomic min ----
    int p0 = pStart + tid * KPOS;
    if (p0 < P) {
        int lo = 0, hi = n_seg - 1;
        while (lo < hi) {
            int mid = (lo + hi + 1) >> 1;
            if (__ldg(&cum[mid]) <= p0) lo = mid; else hi = mid - 1;
        }
        int seg = lo;
        int nxt = __ldg(&cum[seg + 1]);
        unsigned lm = 0xFFFFFFFFu;
#pragma unroll
        for (int k = 0; k < KPOS; ++k) {
            int p = p0 + k;
            if (p >= P) break;
            while (p >= nxt) {
                if (lm != 0xFFFFFFFFu) atomicMin(&g_mins[seg], lm);
                lm = 0xFFFFFFFFu;
                ++seg;
                nxt = __ldg(&cum[seg + 1]);
            }
            if (p + MLEN <= nxt) lm = min(lm, enc_f(dist[k]));
        }
        if (lm != 0xFFFFFFFFu) atomicMin(&g_mins[seg], lm);
    }

    // ---- fused finalize: last block does min/max + scale + linear ----
    __threadfence();
    __syncthreads();
    __shared__ int s_last;
    __shared__ float rlo[8], rhi[8];
    if (tid == 0) s_last = (atomicAdd(&g_done, 1) == (int)gridDim.x - 1);
    __syncthreads();
    if (s_last) {
        __threadfence();
        float flo = 3.0e38f, fhi = -3.0e38f;
        for (int i = tid; i < n_seg; i += TPB) {
            unsigned u = g_mins[i];
            float v = (u == 0xFFFFFFFFu) ? 1.0e30f : dec_f(u);
            flo = fminf(flo, v);
            fhi = fmaxf(fhi, v);
        }
#pragma unroll
        for (int o = 16; o; o >>= 1) {
            flo = fminf(flo, __shfl_xor_sync(0xFFFFFFFFu, flo, o));
            fhi = fmaxf(fhi, __shfl_xor_sync(0xFFFFFFFFu, fhi, o));
        }
        if ((tid & 31) == 0) { rlo[tid >> 5] = flo; rhi[tid >> 5] = fhi; }
        __syncthreads();
        if (tid < 32) {
            flo = (tid < 8) ? rlo[tid] : 3.0e38f;
            fhi = (tid < 8) ? rhi[tid] : -3.0e38f;
#pragma unroll
            for (int o = 4; o; o >>= 1) {
                flo = fminf(flo, __shfl_xor_sync(0xFFFFFFFFu, flo, o));
                fhi = fmaxf(fhi, __shfl_xor_sync(0xFFFFFFFFu, fhi, o));
            }
            if (tid == 0) { rlo[0] = flo; rhi[0] = fhi; }
        }
        __syncthreads();
        flo = rlo[0]; fhi = rhi[0];
        const float denom = fhi - flo + 1e-16f;
        const float w0 = lin_w[0], w1 = lin_w[1];
        const float b0 = lin_b[0], b1 = lin_b[1];
        for (int i = tid; i < n_seg; i += TPB) {
            unsigned u = g_mins[i];
            float v = (u == 0xFFFFFFFFu) ? 1.0e30f : dec_f(u);
            float sc = (v - flo) / denom;
            out[2 * i + 0] = fmaf(sc, w0, b0);
            out[2 * i + 1] = fmaf(sc, w1, b1);
        }
        if (tid == 0) g_done = 0;
    }
}

extern "C" void kernel_launch(void* const* d_in, const int* in_sizes, int n_in,
                              void* d_out, int out_size)
{
    const float* X     = (const float*)d_in[0];
    const float* query = (const float*)d_in[1];
    const float* lin_w = (const float*)d_in[2];
    const float* lin_b = (const float*)d_in[3];
    const int*   cum   = (const int*)d_in[4];
    float* out = (float*)d_out;

    const int T     = in_sizes[0] / DIM;
    const int n_seg = in_sizes[4] - 1;
    const int P     = T - MLEN + 1;

    cudaFuncSetAttribute(shapelet_main_kernel,
                         cudaFuncAttributeMaxDynamicSharedMemorySize, SM_TOTAL);

    init_mins_kernel<<<(n_seg + 255) / 256, 256>>>(n_seg);

    const int nblocks = (P + TILE_POS - 1) / TILE_POS;
    shapelet_main_kernel<<<nblocks, TPB, SM_TOTAL>>>(
        X, query, cum, lin_w, lin_b, out, T, n_seg, P);
}

// round 9
// speedup vs baseline: 2.0341x; 1.2956x over previous
#include <cuda_runtime.h>
#include <stdint.h>

// Problem constants: D=64, M=32, output fp32 [n_seg, 2]
#define DIM      64
#define MLEN     32
#define DC       2                      // d-rows per chunk
#define NCHUNK   (DIM / DC)             // 32
#define TPB      256
#define KPOS     8                      // positions per thread
#define TILE_POS (TPB * KPOS)           // 2048 window starts per block
#define TILE_COLS (TILE_POS + MLEN)     // 2080 columns per tile row
#define NGRAN    (TILE_COLS / 4)        // 520 16B granules per row
// pad 1 granule (16B) per 8 granules (128B): conflict-free for stride-2-granule lanes
#define RSTRIDE  (TILE_COLS + (TILE_COLS / 32) * 4)   // 2340 floats

#define MAX_SEG  8192

__device__ unsigned g_mins[MAX_SEG];
__device__ int g_done;
__constant__ float c_q[DIM * MLEN];     // query, served by the constant port (not LSU)

// order-preserving float -> uint mapping (ascending)
__device__ __forceinline__ unsigned enc_f(float f) {
    int b = __float_as_int(f);
    return (unsigned)(b >= 0 ? (b | 0x80000000) : ~b);
}
__device__ __forceinline__ float dec_f(unsigned u) {
    int b = (u & 0x80000000u) ? (int)(u & 0x7FFFFFFFu) : ~(int)u;
    return __int_as_float(b);
}

__device__ __forceinline__ unsigned long long ffma2(unsigned long long a,
                                                    unsigned long long b,
                                                    unsigned long long c) {
    unsigned long long d;
    asm("fma.rn.f32x2 %0, %1, %2, %3;" : "=l"(d) : "l"(a), "l"(b), "l"(c));
    return d;
}
__device__ __forceinline__ unsigned long long pk2(float lo, float hi) {
    unsigned long long r;
    asm("mov.b64 %0, {%1, %2};" : "=l"(r) : "f"(lo), "f"(hi));
    return r;
}
__device__ __forceinline__ void up2(unsigned long long v, float& a, float& b) {
    asm("mov.b64 {%0, %1}, %2;" : "=f"(a), "=f"(b) : "l"(v));
}
__device__ __forceinline__ void cpa16(uint32_t dst, const void* src) {
    asm volatile("cp.async.cg.shared.global [%0], [%1], 16;" :: "r"(dst), "l"(src));
}
__device__ __forceinline__ void cpa_commit() {
    asm volatile("cp.async.commit_group;" ::: "memory");
}
__device__ __forceinline__ void cpa_wait1() {
    asm volatile("cp.async.wait_group 1;" ::: "memory");
}

__global__ void init_mins_kernel(int n) {
    int i = blockIdx.x * blockDim.x + threadIdx.x;
    if (i < n) g_mins[i] = 0xFFFFFFFFu;
}

// smem float layout:
//   tile : [2][DC][RSTRIDE]          floats 0 .. 9360
//   s_sh : [RSTRIDE]                 floats 9360 .. 11700
#define SM_SSH   (2 * DC * RSTRIDE)
#define SM_TOTAL ((SM_SSH + RSTRIDE) * 4)

__global__ __launch_bounds__(TPB, 4) void shapelet_main_kernel(
    const float* __restrict__ X,      // [DIM, T]
    const int*   __restrict__ cum,    // [n_seg+1]
    const float* __restrict__ lin_w,
    const float* __restrict__ lin_b,
    float* __restrict__ out,
    int T, int n_seg, int P)
{
    extern __shared__ float sh[];
    float* s_sh = sh + SM_SSH;
    const uint32_t sbase = (uint32_t)__cvta_generic_to_shared(sh);

    const int tid    = threadIdx.x;
    const int pStart = blockIdx.x * TILE_POS;
    const bool inb   = (pStart + TILE_COLS <= T);

    unsigned long long accE[4], accO[5], sq[4];
#pragma unroll
    for (int a = 0; a < 4; ++a) { accE[a] = 0ull; sq[a] = 0ull; }
#pragma unroll
    for (int a = 0; a < 5; ++a) accO[a] = 0ull;
    float tacc = 0.f;                       // tail col (warp 0 only)
    const int tailpc = (2048 + tid) + (((2048 + tid) >> 5) << 2);

    // ---- prefetch one chunk into buffer b ----
    auto prefetch = [&](int dc, int b) {
#pragma unroll
        for (int r = 0; r < DC; ++r) {
            const float* src = X + (size_t)(dc * DC + r) * T + pStart;
            uint32_t drow = sbase + (uint32_t)((b * DC + r) * RSTRIDE) * 4u;
            float* growp = sh + (b * DC + r) * RSTRIDE;
            if (inb) {
                for (int gi = tid; gi < NGRAN; gi += TPB) {
                    int pf = (gi + (gi >> 3)) << 2;
                    cpa16(drow + (uint32_t)pf * 4u, src + (gi << 2));
                }
            } else {
                for (int gi = tid; gi < NGRAN; gi += TPB) {
                    int pf = (gi + (gi >> 3)) << 2;
                    int gc = pStart + (gi << 2);
                    if (gc + 4 <= T) {
                        cpa16(drow + (uint32_t)pf * 4u, src + (gi << 2));
                    } else {
                        float4 z;
                        z.x = (gc + 0 < T) ? src[(gi << 2) + 0] : 0.f;
                        z.y = (gc + 1 < T) ? src[(gi << 2) + 1] : 0.f;
                        z.z = (gc + 2 < T) ? src[(gi << 2) + 2] : 0.f;
                        z.w = (gc + 3 < T) ? src[(gi << 2) + 3] : 0.f;
                        *(float4*)(growp + pf) = z;
                    }
                }
            }
        }
    };

    prefetch(0, 0);
    cpa_commit();

#pragma unroll 1
    for (int dc = 0; dc < NCHUNK; ++dc) {
        const int par = dc & 1;
        if (dc + 1 < NCHUNK) prefetch(dc + 1, (dc + 1) & 1);
        cpa_commit();
        cpa_wait1();
        __syncthreads();

        const float* tb = sh + par * DC * RSTRIDE;
#pragma unroll
        for (int r = 0; r < DC; ++r) {
            const float* rowp = tb + r * RSTRIDE;
#pragma unroll
            for (int h = 0; h < 2; ++h) {
                unsigned long long xq[12];
#pragma unroll
                for (int i = 0; i < 6; ++i) {
                    int g = 2 * tid + 4 * h + i;
                    int pf = (g + (g >> 3)) << 2;
                    ulonglong2 vv = *(const ulonglong2*)(rowp + pf);
                    xq[2 * i] = vv.x; xq[2 * i + 1] = vv.y;
                }
                if (h == 0) {
#pragma unroll
                    for (int j = 0; j < 4; ++j)
                        sq[j] = ffma2(xq[j], xq[j], sq[j]);
                }
                // query taps from constant memory (uniform LDC; off the crossbar)
                const float* qrow = c_q + (dc * DC + r) * MLEN + 16 * h;
#pragma unroll
                for (int t2 = 0; t2 < 8; ++t2) {
                    float qev = qrow[2 * t2];
                    float qov = qrow[2 * t2 + 1];
                    unsigned long long qe = pk2(qev, qev);
                    unsigned long long qo = pk2(qov, qov);
#pragma unroll
                    for (int a = 0; a < 4; ++a)
                        accE[a] = ffma2(xq[t2 + a], qe, accE[a]);
#pragma unroll
                    for (int a = 0; a < 5; ++a)
                        accO[a] = ffma2(xq[t2 + a], qo, accO[a]);
                }
            }
        }
        // tail columns 2048..2079: squared sums by warp 0 (register-resident)
        if (tid < 32) {
#pragma unroll
            for (int r = 0; r < DC; ++r) {
                float v = tb[r * RSTRIDE + tailpc];
                tacc = fmaf(v, v, tacc);
            }
        }
        __syncthreads();
    }

    // ---- write per-column squared sums once ----
    {
        int c0 = 8 * tid;
        int pc = c0 + ((c0 >> 5) << 2);
        ulonglong2 a; a.x = sq[0]; a.y = sq[1];
        ulonglong2 b; b.x = sq[2]; b.y = sq[3];
        *(ulonglong2*)(s_sh + pc) = a;
        *(ulonglong2*)(s_sh + pc + 4) = b;
    }
    if (tid < 32) s_sh[tailpc] = tacc;
    __syncthreads();

    // ---- assemble distances ----
    float sv[KPOS + MLEN];
#pragma unroll
    for (int i = 0; i < 10; ++i) {
        int g = 2 * tid + i;
        int pf = (g + (g >> 3)) << 2;
        float4 f = *(const float4*)(s_sh + pf);
        sv[4 * i + 0] = f.x; sv[4 * i + 1] = f.y;
        sv[4 * i + 2] = f.z; sv[4 * i + 3] = f.w;
    }
    float qx[KPOS];
    {
        float el[4], eh[4], ol[5], oh[5];
#pragma unroll
        for (int a = 0; a < 4; ++a) up2(accE[a], el[a], eh[a]);
#pragma unroll
        for (int a = 0; a < 5; ++a) up2(accO[a], ol[a], oh[a]);
#pragma unroll
        for (int a = 0; a < 4; ++a) {
            qx[2 * a]     = el[a] + oh[a];
            qx[2 * a + 1] = eh[a] + ol[a + 1];
        }
    }
    float dist[KPOS];
    {
        float w = 0.f;
#pragma unroll
        for (int j = 0; j < MLEN; ++j) w += sv[j];
        dist[0] = w - 2.f * qx[0];
#pragma unroll
        for (int k = 1; k < KPOS; ++k) {
            w += sv[k - 1 + MLEN] - sv[k - 1];
            dist[k] = w - 2.f * qx[k];
        }
    }

    // ---- segment assignment + atomic min ----
    int p0 = pStart + tid * KPOS;
    if (p0 < P) {
        int lo = 0, hi = n_seg - 1;
        while (lo < hi) {
            int mid = (lo + hi + 1) >> 1;
            if (__ldg(&cum[mid]) <= p0) lo = mid; else hi = mid - 1;
        }
        int seg = lo;
        int nxt = __ldg(&cum[seg + 1]);
        unsigned lm = 0xFFFFFFFFu;
#pragma unroll
        for (int k = 0; k < KPOS; ++k) {
            int p = p0 + k;
            if (p >= P) break;
            while (p >= nxt) {
                if (lm != 0xFFFFFFFFu) atomicMin(&g_mins[seg], lm);
                lm = 0xFFFFFFFFu;
                ++seg;
                nxt = __ldg(&cum[seg + 1]);
            }
            if (p + MLEN <= nxt) lm = min(lm, enc_f(dist[k]));
        }
        if (lm != 0xFFFFFFFFu) atomicMin(&g_mins[seg], lm);
    }

    // ---- fused finalize: last block does min/max + scale + linear ----
    __threadfence();
    __syncthreads();
    __shared__ int s_last;
    __shared__ float rlo[8], rhi[8];
    if (tid == 0) s_last = (atomicAdd(&g_done, 1) == (int)gridDim.x - 1);
    __syncthreads();
    if (s_last) {
        __threadfence();
        float flo = 3.0e38f, fhi = -3.0e38f;
        for (int i = tid; i < n_seg; i += TPB) {
            unsigned u = g_mins[i];
            float v = (u == 0xFFFFFFFFu) ? 1.0e30f : dec_f(u);
            flo = fminf(flo, v);
            fhi = fmaxf(fhi, v);
        }
#pragma unroll
        for (int o = 16; o; o >>= 1) {
            flo = fminf(flo, __shfl_xor_sync(0xFFFFFFFFu, flo, o));
            fhi = fmaxf(fhi, __shfl_xor_sync(0xFFFFFFFFu, fhi, o));
        }
        if ((tid & 31) == 0) { rlo[tid >> 5] = flo; rhi[tid >> 5] = fhi; }
        __syncthreads();
        if (tid < 32) {
            flo = (tid < 8) ? rlo[tid] : 3.0e38f;
            fhi = (tid < 8) ? rhi[tid] : -3.0e38f;
#pragma unroll
            for (int o = 4; o; o >>= 1) {
                flo = fminf(flo, __shfl_xor_sync(0xFFFFFFFFu, flo, o));
                fhi = fmaxf(fhi, __shfl_xor_sync(0xFFFFFFFFu, fhi, o));
            }
            if (tid == 0) { rlo[0] = flo; rhi[0] = fhi; }
        }
        __syncthreads();
        flo = rlo[0]; fhi = rhi[0];
        const float denom = fhi - flo + 1e-16f;
        const float w0 = lin_w[0], w1 = lin_w[1];
        const float b0 = lin_b[0], b1 = lin_b[1];
        for (int i = tid; i < n_seg; i += TPB) {
            unsigned u = g_mins[i];
            float v = (u == 0xFFFFFFFFu) ? 1.0e30f : dec_f(u);
            float sc = (v - flo) / denom;
            out[2 * i + 0] = fmaf(sc, w0, b0);
            out[2 * i + 1] = fmaf(sc, w1, b1);
        }
        if (tid == 0) g_done = 0;
    }
}

extern "C" void kernel_launch(void* const* d_in, const int* in_sizes, int n_in,
                              void* d_out, int out_size)
{
    const float* X     = (const float*)d_in[0];
    const float* query = (const float*)d_in[1];
    const float* lin_w = (const float*)d_in[2];
    const float* lin_b = (const float*)d_in[3];
    const int*   cum   = (const int*)d_in[4];
    float* out = (float*)d_out;

    const int T     = in_sizes[0] / DIM;
    const int n_seg = in_sizes[4] - 1;
    const int P     = T - MLEN + 1;

    cudaFuncSetAttribute(shapelet_main_kernel,
                         cudaFuncAttributeMaxDynamicSharedMemorySize, SM_TOTAL);

    // stage query into constant memory (D2D async: graph-capturable)
    cudaMemcpyToSymbolAsync(c_q, query, DIM * MLEN * sizeof(float), 0,
                            cudaMemcpyDeviceToDevice, 0);

    init_mins_kernel<<<(n_seg + 255) / 256, 256>>>(n_seg);

    const int nblocks = (P + TILE_POS - 1) / TILE_POS;
    shapelet_main_kernel<<<nblocks, TPB, SM_TOTAL>>>(
        X, cum, lin_w, lin_b, out, T, n_seg, P);
}